// round 6
// baseline (speedup 1.0000x reference)
#include <cuda_runtime.h>

// ---------------- problem constants ----------------
#define SB    2304          // S = H*W
#define BSR   4608          // B*S
#define DD    64
#define NHH   8
#define HDD   8
#define FFD   2048
#define NLAYER 8
#define KS    21
#define KK2   441           // KSIZE*KSIZE
#define HH    48
#define WWD   48
#define CC    3
#define BB    2
#define EPSV  1e-5f

// ---------------- scratch (static device memory: allowed) ----------------
__device__ float g_y[BSR * DD];
__device__ float g_qkv[BSR * 3 * DD];
__device__ float g_attno[BSR * DD];
__device__ float g_res[BSR * DD];
__device__ float g_ff[BSR * FFD];     // also reused for last-layer scores (BSR*441)

// ---------------- fast exp (no MUFU) ----------------
// exp(x) for x <= 0, rel err ~2e-6. Magic-constant round-to-nearest + deg-5 poly for 2^f.
__device__ __forceinline__ float fexp(float x) {
    x = fmaxf(x, -60.0f);
    float t = x * 1.4426950408889634f;           // x * log2(e), in [-86.6, 0]
    float r = t + 12582912.0f;                   // 1.5*2^23: round-to-nearest
    int   n = __float_as_int(r) - 0x4B400000;    // integer part
    float nf = r - 12582912.0f;
    float f = t - nf;                            // f in [-0.5, 0.5]
    // 2^f Taylor deg 5
    float p = 0.0013333558f;
    p = fmaf(p, f, 0.0096181291f);
    p = fmaf(p, f, 0.0555041087f);
    p = fmaf(p, f, 0.2402265070f);
    p = fmaf(p, f, 0.6931471806f);
    p = fmaf(p, f, 1.0f);
    return __int_as_float(__float_as_int(p) + (n << 23));
}

// ---------------- conv 3x3 (pad 1) + BN + ReLU, output [B,S,D] ----------------
__global__ __launch_bounds__(256) void conv_bn_relu(
    const float* __restrict__ x, const float* __restrict__ w,
    const float* __restrict__ cb, const float* __restrict__ gma,
    const float* __restrict__ bta, const float* __restrict__ mean,
    const float* __restrict__ var, float* __restrict__ y)
{
    int idx = blockIdx.x * 256 + threadIdx.x;
    if (idx >= BSR * DD) return;
    int d = idx & 63;
    int s = (idx >> 6) % SB;
    int b = idx / (SB * DD);
    int hh = s / WWD, ww = s % WWD;
    float sum = cb[d];
    #pragma unroll
    for (int ci = 0; ci < 3; ci++) {
        #pragma unroll
        for (int kh = 0; kh < 3; kh++) {
            int ih = hh + kh - 1;
            if ((unsigned)ih >= HH) continue;
            #pragma unroll
            for (int kw = 0; kw < 3; kw++) {
                int iw = ww + kw - 1;
                if ((unsigned)iw >= WWD) continue;
                sum += x[((b * CC + ci) * HH + ih) * WWD + iw] *
                       w[((d * CC + ci) * 3 + kh) * 3 + kw];
            }
        }
    }
    sum = (sum - mean[d]) * rsqrtf(var[d] + EPSV) * gma[d] + bta[d];
    y[idx] = fmaxf(sum, 0.0f);
}

// ---------------- GEMM: C[M,N] = A[M,K] @ W[N,K]^T (+bias, opt relu, opt split-K) ----------------
// 64x64 tile, BK=16, 256 threads, 4x4 per-thread register tile.
// M must be a multiple of 64 (M=4608 always). N arbitrary. K multiple of 16*gridDim.z.
__global__ __launch_bounds__(256) void gemm_kernel(
    const float* __restrict__ A, const float* __restrict__ W,
    const float* __restrict__ bias, float* __restrict__ C,
    int M, int N, int K, int relu)
{
    __shared__ float As[16][68];
    __shared__ float Ws[16][68];
    int tid = threadIdx.x;
    int tx = tid & 15, ty = tid >> 4;
    int rowBase = blockIdx.y * 64;
    int nBase = blockIdx.x * 64;
    int kk = tid & 15;
    int ib = tid >> 4;
    int kChunk = K / gridDim.z;
    int kStart = blockIdx.z * kChunk;

    float acc[4][4] = {};
    for (int k0 = kStart; k0 < kStart + kChunk; k0 += 16) {
        __syncthreads();
        #pragma unroll
        for (int j = 0; j < 4; j++) {
            int i = ib + j * 16;
            As[kk][i] = A[(rowBase + i) * K + k0 + kk];
            int n = nBase + i;
            Ws[kk][i] = (n < N) ? W[n * K + k0 + kk] : 0.0f;
        }
        __syncthreads();
        #pragma unroll
        for (int k = 0; k < 16; k++) {
            float4 a4 = *(const float4*)&As[k][ty * 4];
            float4 b4 = *(const float4*)&Ws[k][tx * 4];
            float av[4] = {a4.x, a4.y, a4.z, a4.w};
            float bv[4] = {b4.x, b4.y, b4.z, b4.w};
            #pragma unroll
            for (int u = 0; u < 4; u++)
                #pragma unroll
                for (int v = 0; v < 4; v++)
                    acc[u][v] = fmaf(av[u], bv[v], acc[u][v]);
        }
    }

    if (gridDim.z == 1) {
        #pragma unroll
        for (int u = 0; u < 4; u++) {
            int r = rowBase + ty * 4 + u;
            #pragma unroll
            for (int v = 0; v < 4; v++) {
                int n = nBase + tx * 4 + v;
                if (n < N) {
                    float val = acc[u][v] + bias[n];
                    if (relu) val = fmaxf(val, 0.0f);
                    C[r * N + n] = val;
                }
            }
        }
    } else {
        #pragma unroll
        for (int u = 0; u < 4; u++) {
            int r = rowBase + ty * 4 + u;
            #pragma unroll
            for (int v = 0; v < 4; v++) {
                int n = nBase + tx * 4 + v;
                if (n < N) atomicAdd(&C[r * N + n], acc[u][v]);
            }
        }
    }
}

// init C[i] = bias[i % 64]  (for split-K accumulation)
__global__ __launch_bounds__(256) void init_bias64(float* __restrict__ C,
                                                   const float* __restrict__ bias, int total)
{
    int i = blockIdx.x * 256 + threadIdx.x;
    if (i < total) C[i] = bias[i & 63];
}

// ---------------- attention: streaming online softmax ----------------
// grid (B*NH, S/128), block 128. Each thread owns one query row.
__global__ __launch_bounds__(128) void attention_kernel(
    const float* __restrict__ qkv, float* __restrict__ o)
{
    __shared__ float Kt[128][8];
    __shared__ float Vt[128][8];
    int bh = blockIdx.x;
    int b = bh >> 3, h = bh & 7;
    int qbase = blockIdx.y * 128;
    int tid = threadIdx.x;
    int srow = b * SB + qbase + tid;

    const float* qp = qkv + srow * 192 + h * 8;
    float q[8];
    const float scale = 0.35355339059327373f;   // 1/sqrt(8)
    #pragma unroll
    for (int j = 0; j < 8; j++) q[j] = qp[j] * scale;

    float m = -1e30f, sum = 0.0f;
    float acc[8] = {};

    for (int t = 0; t < SB; t += 128) {
        __syncthreads();
        {
            const float* kp = qkv + (b * SB + t + tid) * 192 + 64 + h * 8;
            float4 k0 = *(const float4*)kp;
            float4 k1 = *(const float4*)(kp + 4);
            float4 v0 = *(const float4*)(kp + 64);
            float4 v1 = *(const float4*)(kp + 68);
            *(float4*)&Kt[tid][0] = k0; *(float4*)&Kt[tid][4] = k1;
            *(float4*)&Vt[tid][0] = v0; *(float4*)&Vt[tid][4] = v1;
        }
        __syncthreads();
        #pragma unroll 4
        for (int kidx = 0; kidx < 128; kidx++) {
            float4 ka = *(const float4*)&Kt[kidx][0];
            float4 kb = *(const float4*)&Kt[kidx][4];
            float s = q[0]*ka.x + q[1]*ka.y + q[2]*ka.z + q[3]*ka.w
                    + q[4]*kb.x + q[5]*kb.y + q[6]*kb.z + q[7]*kb.w;
            if (s > m) {
                float c = fexp(m - s);
                sum *= c;
                #pragma unroll
                for (int j = 0; j < 8; j++) acc[j] *= c;
                m = s;
            }
            float p = fexp(s - m);
            sum += p;
            float4 va = *(const float4*)&Vt[kidx][0];
            float4 vb = *(const float4*)&Vt[kidx][4];
            acc[0] = fmaf(p, va.x, acc[0]); acc[1] = fmaf(p, va.y, acc[1]);
            acc[2] = fmaf(p, va.z, acc[2]); acc[3] = fmaf(p, va.w, acc[3]);
            acc[4] = fmaf(p, vb.x, acc[4]); acc[5] = fmaf(p, vb.y, acc[5]);
            acc[6] = fmaf(p, vb.z, acc[6]); acc[7] = fmaf(p, vb.w, acc[7]);
        }
    }
    float inv = 1.0f / sum;
    float* op = o + srow * 64 + h * 8;
    #pragma unroll
    for (int j = 0; j < 8; j++) op[j] = acc[j] * inv;
}

// ---------------- residual add + LayerNorm (rows of 64), warp per row ----------------
__global__ __launch_bounds__(256) void add_ln_kernel(
    float* __restrict__ y, const float* __restrict__ r,
    const float* __restrict__ g, const float* __restrict__ b)
{
    int row = blockIdx.x * 8 + (threadIdx.x >> 5);
    int lane = threadIdx.x & 31;
    float z0 = y[row * 64 + lane] + r[row * 64 + lane];
    float z1 = y[row * 64 + 32 + lane] + r[row * 64 + 32 + lane];
    float s = z0 + z1;
    float ss = z0 * z0 + z1 * z1;
    #pragma unroll
    for (int off = 16; off; off >>= 1) {
        s  += __shfl_xor_sync(0xFFFFFFFFu, s, off);
        ss += __shfl_xor_sync(0xFFFFFFFFu, ss, off);
    }
    float mean = s * (1.0f / 64.0f);
    float var = ss * (1.0f / 64.0f) - mean * mean;
    float inv = rsqrtf(var + EPSV);
    y[row * 64 + lane]      = (z0 - mean) * inv * g[lane]      + b[lane];
    y[row * 64 + 32 + lane] = (z1 - mean) * inv * g[32 + lane] + b[32 + lane];
}

// ---------------- final softmax over 441 + transpose to [B,441,S] ----------------
__global__ __launch_bounds__(128) void softmax_t_kernel(
    const float* __restrict__ sc, float* __restrict__ outK)
{
    __shared__ float red[128];
    int row = blockIdx.x;                 // 0..4607
    int b = row / SB, s = row % SB;
    int tid = threadIdx.x;
    float v[4];
    float mx = -1e30f;
    #pragma unroll
    for (int i = 0; i < 4; i++) {
        int p = tid + i * 128;
        v[i] = (p < KK2) ? sc[row * KK2 + p] : -1e30f;
        mx = fmaxf(mx, v[i]);
    }
    red[tid] = mx; __syncthreads();
    for (int o = 64; o; o >>= 1) { if (tid < o) red[tid] = fmaxf(red[tid], red[tid + o]); __syncthreads(); }
    float m = red[0]; __syncthreads();
    float sum = 0.0f;
    #pragma unroll
    for (int i = 0; i < 4; i++) {
        int p = tid + i * 128;
        v[i] = (p < KK2) ? __expf(v[i] - m) : 0.0f;
        sum += v[i];
    }
    red[tid] = sum; __syncthreads();
    for (int o = 64; o; o >>= 1) { if (tid < o) red[tid] += red[tid + o]; __syncthreads(); }
    float inv = 1.0f / red[0];
    #pragma unroll
    for (int i = 0; i < 4; i++) {
        int p = tid + i * 128;
        if (p < KK2) outK[(b * KK2 + p) * SB + s] = v[i] * inv;
    }
}

// ---------------- apply predicted kernel to reflect-padded x ----------------
__global__ __launch_bounds__(256) void apply_kernel(
    const float* __restrict__ x, const float* __restrict__ kern, float* __restrict__ out)
{
    int idx = blockIdx.x * 256 + threadIdx.x;
    if (idx >= BB * CC * HH * WWD) return;
    int ww = idx % WWD;
    int hh = (idx / WWD) % HH;
    int c = (idx / (HH * WWD)) % CC;
    int b = idx / (CC * HH * WWD);
    const float* kb = kern + b * KK2 * SB + hh * WWD + ww;
    const float* xb = x + (b * CC + c) * HH * WWD;
    float acc = 0.0f;
    #pragma unroll 1
    for (int kh = 0; kh < KS; kh++) {
        int ih = hh + kh - 10;
        if (ih < 0) ih = -ih;
        else if (ih >= HH) ih = 2 * HH - 2 - ih;
        const float* xr = xb + ih * WWD;
        #pragma unroll
        for (int kw = 0; kw < KS; kw++) {
            int iw = ww + kw - 10;
            if (iw < 0) iw = -iw;
            else if (iw >= WWD) iw = 2 * WWD - 2 - iw;
            acc = fmaf(xr[iw], kb[(kh * KS + kw) * SB], acc);
        }
    }
    out[idx] = acc;
}

// ---------------- host launcher ----------------
extern "C" void kernel_launch(void* const* d_in, const int* in_sizes, int n_in,
                              void* d_out, int out_size)
{
    const float* x        = (const float*)d_in[0];
    const float* conv1_w  = (const float*)d_in[1];
    const float* conv1_b  = (const float*)d_in[2];
    const float* bn_gamma = (const float*)d_in[3];
    const float* bn_beta  = (const float*)d_in[4];
    const float* bn_mean  = (const float*)d_in[5];
    const float* bn_var   = (const float*)d_in[6];
    const float* attn_in_w  = (const float*)d_in[7];
    const float* attn_in_b  = (const float*)d_in[8];
    const float* attn_out_w = (const float*)d_in[9];
    const float* attn_out_b = (const float*)d_in[10];
    const float* lin1_w   = (const float*)d_in[11];
    const float* lin1_b   = (const float*)d_in[12];
    const float* lin2_w   = (const float*)d_in[13];
    const float* lin2_b   = (const float*)d_in[14];
    const float* ln1_g    = (const float*)d_in[15];
    const float* ln1_b    = (const float*)d_in[16];
    const float* ln2_g    = (const float*)d_in[17];
    const float* ln2_b    = (const float*)d_in[18];
    const float* last_w   = (const float*)d_in[19];
    const float* last_b   = (const float*)d_in[20];

    float* out = (float*)d_out;                       // [B,C,H,W] = 13824
    float* kern = out + BB * CC * HH * WWD;           // [B,441,H,W] = 2032128

    float *py, *pqkv, *pattno, *pres, *pff;
    cudaGetSymbolAddress((void**)&py, g_y);
    cudaGetSymbolAddress((void**)&pqkv, g_qkv);
    cudaGetSymbolAddress((void**)&pattno, g_attno);
    cudaGetSymbolAddress((void**)&pres, g_res);
    cudaGetSymbolAddress((void**)&pff, g_ff);

    // stem
    conv_bn_relu<<<(BSR * DD + 255) / 256, 256>>>(x, conv1_w, conv1_b, bn_gamma,
                                                  bn_beta, bn_mean, bn_var, py);

    for (int l = 0; l < NLAYER; l++) {
        // qkv = y @ Win^T + b   [4608,192]
        gemm_kernel<<<dim3(3, BSR / 64, 1), 256>>>(
            py, attn_in_w + l * 192 * DD, attn_in_b + l * 192, pqkv,
            BSR, 192, DD, 0);
        // attention -> attno [4608,64]
        attention_kernel<<<dim3(BB * NHH, SB / 128), 128>>>(pqkv, pattno);
        // proj [4608,64]
        gemm_kernel<<<dim3(1, BSR / 64, 1), 256>>>(
            pattno, attn_out_w + l * DD * DD, attn_out_b + l * DD, pres,
            BSR, DD, DD, 0);
        // y = LN(y + proj)
        add_ln_kernel<<<BSR / 8, 256>>>(py, pres, ln1_g + l * DD, ln1_b + l * DD);
        // ff1 = relu(y @ W1^T + b1)  [4608,2048]
        gemm_kernel<<<dim3(FFD / 64, BSR / 64, 1), 256>>>(
            py, lin1_w + l * FFD * DD, lin1_b + l * FFD, pff,
            BSR, FFD, DD, 1);
        // ff2 = ff1 @ W2^T + b2  [4608,64], split-K over K=2048
        init_bias64<<<(BSR * DD + 255) / 256, 256>>>(pres, lin2_b + l * DD, BSR * DD);
        gemm_kernel<<<dim3(1, BSR / 64, 8), 256>>>(
            pff, lin2_w + l * DD * FFD, lin2_b + l * DD, pres,
            BSR, DD, FFD, 0);
        // y = LN(y + ff2)
        add_ln_kernel<<<BSR / 8, 256>>>(py, pres, ln2_g + l * DD, ln2_b + l * DD);
    }

    // scores = y @ last_w^T + last_b  [4608,441] (into g_ff)
    gemm_kernel<<<dim3((KK2 + 63) / 64, BSR / 64, 1), 256>>>(
        py, last_w, last_b, pff, BSR, KK2, DD, 0);
    // softmax over 441 + transpose -> kern [B,441,S]
    softmax_t_kernel<<<BSR, 128>>>(pff, kern);
    // apply to reflect-padded x -> out [B,C,H,W]
    apply_kernel<<<(BB * CC * HH * WWD + 255) / 256, 256>>>(x, kern, out);
}

// round 7
// speedup vs baseline: 1.2707x; 1.2707x over previous
#include <cuda_runtime.h>

// ---------------- problem constants ----------------
#define SB    2304          // S = H*W
#define BSR   4608          // B*S
#define DD    64
#define NHH   8
#define HDD   8
#define FFD   2048
#define NLAYER 8
#define KS    21
#define KK2   441
#define HH    48
#define WWD   48
#define CC    3
#define BB    2
#define EPSV  1e-5f

// ---------------- scratch ----------------
__device__ float g_y[BSR * DD];
__device__ float g_qkv[BSR * 3 * DD];
__device__ float g_attno[BSR * DD];
__device__ float g_res[BSR * DD];
__device__ float g_ff[BSR * FFD];

// ---------------- fast 2^x (no MUFU), x <= 0, rel err ~4e-5 ----------------
__device__ __forceinline__ float fexp2(float x) {
    x = fmaxf(x, -120.0f);
    float r = x + 12582912.0f;                 // round-to-nearest int
    int   n = __float_as_int(r) - 0x4B400000;
    float f = x - (r - 12582912.0f);           // f in [-0.5, 0.5]
    float p = 0.0096181291f;                   // 2^f Taylor deg 4
    p = fmaf(p, f, 0.0555041087f);
    p = fmaf(p, f, 0.2402265070f);
    p = fmaf(p, f, 0.6931471806f);
    p = fmaf(p, f, 1.0f);
    return __int_as_float(__float_as_int(p) + (n << 23));
}

// ---------------- conv 3x3 + BN + ReLU -> [B,S,D] ----------------
__global__ __launch_bounds__(256) void conv_bn_relu(
    const float* __restrict__ x, const float* __restrict__ w,
    const float* __restrict__ cb, const float* __restrict__ gma,
    const float* __restrict__ bta, const float* __restrict__ mean,
    const float* __restrict__ var, float* __restrict__ y)
{
    int idx = blockIdx.x * 256 + threadIdx.x;
    if (idx >= BSR * DD) return;
    int d = idx & 63;
    int s = (idx >> 6) % SB;
    int b = idx / (SB * DD);
    int hh = s / WWD, ww = s % WWD;
    float sum = cb[d];
    #pragma unroll
    for (int ci = 0; ci < 3; ci++) {
        #pragma unroll
        for (int kh = 0; kh < 3; kh++) {
            int ih = hh + kh - 1;
            if ((unsigned)ih >= HH) continue;
            #pragma unroll
            for (int kw = 0; kw < 3; kw++) {
                int iw = ww + kw - 1;
                if ((unsigned)iw >= WWD) continue;
                sum += x[((b * CC + ci) * HH + ih) * WWD + iw] *
                       w[((d * CC + ci) * 3 + kh) * 3 + kw];
            }
        }
    }
    sum = (sum - mean[d]) * rsqrtf(var[d] + EPSV) * gma[d] + bta[d];
    y[idx] = fmaxf(sum, 0.0f);
}

// ---------------- gemm64: C[M,N] = A[M,64] @ W[N,64]^T + bias, K=64 unrolled ----
// 64x64 tile, 256 threads, 4x4 per-thread. Whole K staged once.
template<int RELU>
__global__ __launch_bounds__(256) void gemm64(
    const float* __restrict__ A, const float* __restrict__ W,
    const float* __restrict__ bias, float* __restrict__ C, int N)
{
    __shared__ float As[64][68];
    __shared__ float Ws[64][68];
    int tid = threadIdx.x;
    int rowBase = blockIdx.y * 64;
    int nBase = blockIdx.x * 64;

    int r = tid >> 2, qd = tid & 3;
    {
        const float* ap = A + (rowBase + r) * 64 + qd * 4;
        #pragma unroll
        for (int j = 0; j < 4; j++) {
            float4 v = *(const float4*)(ap + j * 16);
            int k = qd * 4 + j * 16;
            As[k][r] = v.x; As[k + 1][r] = v.y; As[k + 2][r] = v.z; As[k + 3][r] = v.w;
        }
        int n = nBase + r;
        if (n < N) {
            const float* wp = W + n * 64 + qd * 4;
            #pragma unroll
            for (int j = 0; j < 4; j++) {
                float4 v = *(const float4*)(wp + j * 16);
                int k = qd * 4 + j * 16;
                Ws[k][r] = v.x; Ws[k + 1][r] = v.y; Ws[k + 2][r] = v.z; Ws[k + 3][r] = v.w;
            }
        } else {
            #pragma unroll
            for (int j = 0; j < 4; j++) {
                int k = qd * 4 + j * 16;
                Ws[k][r] = 0.f; Ws[k + 1][r] = 0.f; Ws[k + 2][r] = 0.f; Ws[k + 3][r] = 0.f;
            }
        }
    }
    __syncthreads();

    int tx = tid & 15, ty = tid >> 4;
    float acc[4][4] = {};
    #pragma unroll
    for (int k = 0; k < 64; k++) {
        float4 a4 = *(const float4*)&As[k][ty * 4];
        float4 b4 = *(const float4*)&Ws[k][tx * 4];
        float av[4] = {a4.x, a4.y, a4.z, a4.w};
        float bv[4] = {b4.x, b4.y, b4.z, b4.w};
        #pragma unroll
        for (int u = 0; u < 4; u++)
            #pragma unroll
            for (int v = 0; v < 4; v++)
                acc[u][v] = fmaf(av[u], bv[v], acc[u][v]);
    }

    #pragma unroll
    for (int u = 0; u < 4; u++) {
        int row = rowBase + ty * 4 + u;
        #pragma unroll
        for (int v = 0; v < 4; v++) {
            int n = nBase + tx * 4 + v;
            if (n < N) {
                float val = acc[u][v] + bias[n];
                if (RELU) val = fmaxf(val, 0.0f);
                C[row * N + n] = val;
            }
        }
    }
}

// ---------------- gemm64_ln: Y = LN(Y + A @ W^T + bias), N=64, fused ----------
__global__ __launch_bounds__(256) void gemm64_ln(
    const float* __restrict__ A, const float* __restrict__ W,
    const float* __restrict__ bias, float* __restrict__ Y,
    const float* __restrict__ gam, const float* __restrict__ bet)
{
    __shared__ float As[64][68];
    __shared__ float Ws[64][68];
    int tid = threadIdx.x;
    int rowBase = blockIdx.x * 64;

    int r = tid >> 2, qd = tid & 3;
    {
        const float* ap = A + (rowBase + r) * 64 + qd * 4;
        const float* wp = W + r * 64 + qd * 4;
        #pragma unroll
        for (int j = 0; j < 4; j++) {
            float4 va = *(const float4*)(ap + j * 16);
            float4 vw = *(const float4*)(wp + j * 16);
            int k = qd * 4 + j * 16;
            As[k][r] = va.x; As[k + 1][r] = va.y; As[k + 2][r] = va.z; As[k + 3][r] = va.w;
            Ws[k][r] = vw.x; Ws[k + 1][r] = vw.y; Ws[k + 2][r] = vw.z; Ws[k + 3][r] = vw.w;
        }
    }
    __syncthreads();

    int tx = tid & 15, ty = tid >> 4;
    float acc[4][4] = {};
    #pragma unroll
    for (int k = 0; k < 64; k++) {
        float4 a4 = *(const float4*)&As[k][ty * 4];
        float4 b4 = *(const float4*)&Ws[k][tx * 4];
        float av[4] = {a4.x, a4.y, a4.z, a4.w};
        float bv[4] = {b4.x, b4.y, b4.z, b4.w};
        #pragma unroll
        for (int u = 0; u < 4; u++)
            #pragma unroll
            for (int v = 0; v < 4; v++)
                acc[u][v] = fmaf(av[u], bv[v], acc[u][v]);
    }
    __syncthreads();   // done reading Ws; reuse as Z

    // Z[row][col] = resid + acc + bias
    #pragma unroll
    for (int u = 0; u < 4; u++) {
        int row = ty * 4 + u;
        float4 yv = *(const float4*)&Y[(rowBase + row) * 64 + tx * 4];
        Ws[row][tx * 4 + 0] = acc[u][0] + bias[tx * 4 + 0] + yv.x;
        Ws[row][tx * 4 + 1] = acc[u][1] + bias[tx * 4 + 1] + yv.y;
        Ws[row][tx * 4 + 2] = acc[u][2] + bias[tx * 4 + 2] + yv.z;
        Ws[row][tx * 4 + 3] = acc[u][3] + bias[tx * 4 + 3] + yv.w;
    }
    __syncthreads();

    // LN: warp per 8 rows
    int wid = tid >> 5, lane = tid & 31;
    #pragma unroll 1
    for (int i = 0; i < 8; i++) {
        int row = wid * 8 + i;
        float z0 = Ws[row][lane];
        float z1 = Ws[row][lane + 32];
        float s = z0 + z1;
        float ss = z0 * z0 + z1 * z1;
        #pragma unroll
        for (int off = 16; off; off >>= 1) {
            s  += __shfl_xor_sync(0xFFFFFFFFu, s, off);
            ss += __shfl_xor_sync(0xFFFFFFFFu, ss, off);
        }
        float mean = s * (1.0f / 64.0f);
        float var = ss * (1.0f / 64.0f) - mean * mean;
        float inv = rsqrtf(var + EPSV);
        Y[(rowBase + row) * 64 + lane]      = (z0 - mean) * inv * gam[lane]      + bet[lane];
        Y[(rowBase + row) * 64 + 32 + lane] = (z1 - mean) * inv * gam[32 + lane] + bet[32 + lane];
    }
}

// ---------------- generic GEMM (used for lin2 split-K) ----------------
__global__ __launch_bounds__(256) void gemm_kernel(
    const float* __restrict__ A, const float* __restrict__ W,
    const float* __restrict__ bias, float* __restrict__ C,
    int M, int N, int K, int relu)
{
    __shared__ float As[16][68];
    __shared__ float Ws[16][68];
    int tid = threadIdx.x;
    int tx = tid & 15, ty = tid >> 4;
    int rowBase = blockIdx.y * 64;
    int nBase = blockIdx.x * 64;
    int kk = tid & 15;
    int ib = tid >> 4;
    int kChunk = K / gridDim.z;
    int kStart = blockIdx.z * kChunk;

    float acc[4][4] = {};
    for (int k0 = kStart; k0 < kStart + kChunk; k0 += 16) {
        __syncthreads();
        #pragma unroll
        for (int j = 0; j < 4; j++) {
            int i = ib + j * 16;
            As[kk][i] = A[(rowBase + i) * K + k0 + kk];
            int n = nBase + i;
            Ws[kk][i] = (n < N) ? W[n * K + k0 + kk] : 0.0f;
        }
        __syncthreads();
        #pragma unroll
        for (int k = 0; k < 16; k++) {
            float4 a4 = *(const float4*)&As[k][ty * 4];
            float4 b4 = *(const float4*)&Ws[k][tx * 4];
            float av[4] = {a4.x, a4.y, a4.z, a4.w};
            float bv[4] = {b4.x, b4.y, b4.z, b4.w};
            #pragma unroll
            for (int u = 0; u < 4; u++)
                #pragma unroll
                for (int v = 0; v < 4; v++)
                    acc[u][v] = fmaf(av[u], bv[v], acc[u][v]);
        }
    }

    if (gridDim.z == 1) {
        #pragma unroll
        for (int u = 0; u < 4; u++) {
            int r = rowBase + ty * 4 + u;
            #pragma unroll
            for (int v = 0; v < 4; v++) {
                int n = nBase + tx * 4 + v;
                if (n < N) {
                    float val = acc[u][v] + bias[n];
                    if (relu) val = fmaxf(val, 0.0f);
                    C[r * N + n] = val;
                }
            }
        }
    } else {
        #pragma unroll
        for (int u = 0; u < 4; u++) {
            int r = rowBase + ty * 4 + u;
            #pragma unroll
            for (int v = 0; v < 4; v++) {
                int n = nBase + tx * 4 + v;
                if (n < N) atomicAdd(&C[r * N + n], acc[u][v]);
            }
        }
    }
}

__global__ __launch_bounds__(256) void init_bias64(float* __restrict__ C,
                                                   const float* __restrict__ bias, int total)
{
    int i = blockIdx.x * 256 + threadIdx.x;
    if (i < total) C[i] = bias[i & 63];
}

// ---------------- attention: online softmax, 3-way key split per block ------
// grid (B*NH, S/128), block 384. Group g (128 threads) handles key tiles
// tile = g, g+3, ... (6 tiles each of 18). Partials merged via smem.
__global__ __launch_bounds__(384) void attention_kernel(
    const float* __restrict__ qkv, float* __restrict__ o)
{
    __shared__ float Kt[3][128][8];
    __shared__ float Vt[3][128][8];
    __shared__ float Ms[2][128];
    __shared__ float Ss[2][128];
    __shared__ float Accs[2][128][8];

    int tid = threadIdx.x;
    int g = tid >> 7;          // 0..2
    int t = tid & 127;
    int bh = blockIdx.x;
    int b = bh >> 3, h = bh & 7;
    int qbase = blockIdx.y * 128;
    int srow = b * SB + qbase + t;

    // q pre-scaled by 1/sqrt(hd) * log2(e) -> scores in log2 domain
    const float QS = 0.35355339059327373f * 1.4426950408889634f;
    const float* qp = qkv + srow * 192 + h * 8;
    float q[8];
    #pragma unroll
    for (int j = 0; j < 8; j++) q[j] = qp[j] * QS;

    float m = -1e30f, sum = 0.0f;
    float acc[8] = {};

    for (int tile = g; tile < 18; tile += 3) {
        int krow = b * SB + tile * 128 + t;
        const float* kp = qkv + krow * 192 + 64 + h * 8;
        float4 k0 = *(const float4*)kp;
        float4 k1 = *(const float4*)(kp + 4);
        float4 v0 = *(const float4*)(kp + 64);
        float4 v1 = *(const float4*)(kp + 68);
        *(float4*)&Kt[g][t][0] = k0; *(float4*)&Kt[g][t][4] = k1;
        *(float4*)&Vt[g][t][0] = v0; *(float4*)&Vt[g][t][4] = v1;
        asm volatile("bar.sync %0, 128;" :: "r"(g + 1) : "memory");

        #pragma unroll 4
        for (int kk = 0; kk < 128; kk++) {
            float4 ka = *(const float4*)&Kt[g][kk][0];
            float4 kb = *(const float4*)&Kt[g][kk][4];
            float s = q[0]*ka.x + q[1]*ka.y + q[2]*ka.z + q[3]*ka.w
                    + q[4]*kb.x + q[5]*kb.y + q[6]*kb.z + q[7]*kb.w;
            if (s > m) {
                float c = fexp2(m - s);
                sum *= c;
                #pragma unroll
                for (int j = 0; j < 8; j++) acc[j] *= c;
                m = s;
            }
            float p = fexp2(s - m);
            sum += p;
            float4 va = *(const float4*)&Vt[g][kk][0];
            float4 vb = *(const float4*)&Vt[g][kk][4];
            acc[0] = fmaf(p, va.x, acc[0]); acc[1] = fmaf(p, va.y, acc[1]);
            acc[2] = fmaf(p, va.z, acc[2]); acc[3] = fmaf(p, va.w, acc[3]);
            acc[4] = fmaf(p, vb.x, acc[4]); acc[5] = fmaf(p, vb.y, acc[5]);
            acc[6] = fmaf(p, vb.z, acc[6]); acc[7] = fmaf(p, vb.w, acc[7]);
        }
        asm volatile("bar.sync %0, 128;" :: "r"(g + 1) : "memory");
    }

    if (g > 0) {
        Ms[g - 1][t] = m;
        Ss[g - 1][t] = sum;
        #pragma unroll
        for (int j = 0; j < 8; j++) Accs[g - 1][t][j] = acc[j];
    }
    __syncthreads();
    if (g == 0) {
        #pragma unroll
        for (int gg = 0; gg < 2; gg++) {
            float m2 = Ms[gg][t], s2 = Ss[gg][t];
            float M = fmaxf(m, m2);
            float c1 = fexp2(m - M), c2 = fexp2(m2 - M);
            sum = sum * c1 + s2 * c2;
            #pragma unroll
            for (int j = 0; j < 8; j++)
                acc[j] = acc[j] * c1 + Accs[gg][t][j] * c2;
            m = M;
        }
        float inv = 1.0f / sum;
        float* op = o + srow * 64 + h * 8;
        float4 o0 = make_float4(acc[0]*inv, acc[1]*inv, acc[2]*inv, acc[3]*inv);
        float4 o1 = make_float4(acc[4]*inv, acc[5]*inv, acc[6]*inv, acc[7]*inv);
        *(float4*)op = o0;
        *(float4*)(op + 4) = o1;
    }
}

// ---------------- residual add + LayerNorm, warp per row ----------------
__global__ __launch_bounds__(256) void add_ln_kernel(
    float* __restrict__ y, const float* __restrict__ r,
    const float* __restrict__ g, const float* __restrict__ b)
{
    int row = blockIdx.x * 8 + (threadIdx.x >> 5);
    int lane = threadIdx.x & 31;
    float z0 = y[row * 64 + lane] + r[row * 64 + lane];
    float z1 = y[row * 64 + 32 + lane] + r[row * 64 + 32 + lane];
    float s = z0 + z1;
    float ss = z0 * z0 + z1 * z1;
    #pragma unroll
    for (int off = 16; off; off >>= 1) {
        s  += __shfl_xor_sync(0xFFFFFFFFu, s, off);
        ss += __shfl_xor_sync(0xFFFFFFFFu, ss, off);
    }
    float mean = s * (1.0f / 64.0f);
    float var = ss * (1.0f / 64.0f) - mean * mean;
    float inv = rsqrtf(var + EPSV);
    y[row * 64 + lane]      = (z0 - mean) * inv * g[lane]      + b[lane];
    y[row * 64 + 32 + lane] = (z1 - mean) * inv * g[32 + lane] + b[32 + lane];
}

// ---------------- final softmax over 441 + transpose to [B,441,S] ----------
__global__ __launch_bounds__(128) void softmax_t_kernel(
    const float* __restrict__ sc, float* __restrict__ outK)
{
    __shared__ float red[128];
    int row = blockIdx.x;
    int b = row / SB, s = row % SB;
    int tid = threadIdx.x;
    float v[4];
    float mx = -1e30f;
    #pragma unroll
    for (int i = 0; i < 4; i++) {
        int p = tid + i * 128;
        v[i] = (p < KK2) ? sc[row * KK2 + p] : -1e30f;
        mx = fmaxf(mx, v[i]);
    }
    red[tid] = mx; __syncthreads();
    for (int o = 64; o; o >>= 1) { if (tid < o) red[tid] = fmaxf(red[tid], red[tid + o]); __syncthreads(); }
    float m = red[0]; __syncthreads();
    float sum = 0.0f;
    #pragma unroll
    for (int i = 0; i < 4; i++) {
        int p = tid + i * 128;
        v[i] = (p < KK2) ? __expf(v[i] - m) : 0.0f;
        sum += v[i];
    }
    red[tid] = sum; __syncthreads();
    for (int o = 64; o; o >>= 1) { if (tid < o) red[tid] += red[tid + o]; __syncthreads(); }
    float inv = 1.0f / red[0];
    #pragma unroll
    for (int i = 0; i < 4; i++) {
        int p = tid + i * 128;
        if (p < KK2) outK[(b * KK2 + p) * SB + s] = v[i] * inv;
    }
}

// ---------------- apply predicted kernel (reflect pad) ----------------
__global__ __launch_bounds__(256) void apply_kernel(
    const float* __restrict__ x, const float* __restrict__ kern, float* __restrict__ out)
{
    int idx = blockIdx.x * 256 + threadIdx.x;
    if (idx >= BB * CC * HH * WWD) return;
    int ww = idx % WWD;
    int hh = (idx / WWD) % HH;
    int c = (idx / (HH * WWD)) % CC;
    int b = idx / (CC * HH * WWD);
    const float* kb = kern + b * KK2 * SB + hh * WWD + ww;
    const float* xb = x + (b * CC + c) * HH * WWD;
    float acc = 0.0f;
    #pragma unroll 1
    for (int kh = 0; kh < KS; kh++) {
        int ih = hh + kh - 10;
        if (ih < 0) ih = -ih;
        else if (ih >= HH) ih = 2 * HH - 2 - ih;
        const float* xr = xb + ih * WWD;
        #pragma unroll
        for (int kw = 0; kw < KS; kw++) {
            int iw = ww + kw - 10;
            if (iw < 0) iw = -iw;
            else if (iw >= WWD) iw = 2 * WWD - 2 - iw;
            acc = fmaf(xr[iw], kb[(kh * KS + kw) * SB], acc);
        }
    }
    out[idx] = acc;
}

// ---------------- host launcher ----------------
extern "C" void kernel_launch(void* const* d_in, const int* in_sizes, int n_in,
                              void* d_out, int out_size)
{
    const float* x        = (const float*)d_in[0];
    const float* conv1_w  = (const float*)d_in[1];
    const float* conv1_b  = (const float*)d_in[2];
    const float* bn_gamma = (const float*)d_in[3];
    const float* bn_beta  = (const float*)d_in[4];
    const float* bn_mean  = (const float*)d_in[5];
    const float* bn_var   = (const float*)d_in[6];
    const float* attn_in_w  = (const float*)d_in[7];
    const float* attn_in_b  = (const float*)d_in[8];
    const float* attn_out_w = (const float*)d_in[9];
    const float* attn_out_b = (const float*)d_in[10];
    const float* lin1_w   = (const float*)d_in[11];
    const float* lin1_b   = (const float*)d_in[12];
    const float* lin2_w   = (const float*)d_in[13];
    const float* lin2_b   = (const float*)d_in[14];
    const float* ln1_g    = (const float*)d_in[15];
    const float* ln1_b    = (const float*)d_in[16];
    const float* ln2_g    = (const float*)d_in[17];
    const float* ln2_b    = (const float*)d_in[18];
    const float* last_w   = (const float*)d_in[19];
    const float* last_b   = (const float*)d_in[20];

    float* out = (float*)d_out;
    float* kern = out + BB * CC * HH * WWD;

    float *py, *pqkv, *pattno, *pres, *pff;
    cudaGetSymbolAddress((void**)&py, g_y);
    cudaGetSymbolAddress((void**)&pqkv, g_qkv);
    cudaGetSymbolAddress((void**)&pattno, g_attno);
    cudaGetSymbolAddress((void**)&pres, g_res);
    cudaGetSymbolAddress((void**)&pff, g_ff);

    conv_bn_relu<<<(BSR * DD + 255) / 256, 256>>>(x, conv1_w, conv1_b, bn_gamma,
                                                  bn_beta, bn_mean, bn_var, py);

    for (int l = 0; l < NLAYER; l++) {
        // qkv = y @ Win^T + b   [4608,192]
        gemm64<0><<<dim3(3, BSR / 64), 256>>>(
            py, attn_in_w + l * 192 * DD, attn_in_b + l * 192, pqkv, 192);
        // attention -> attno [4608,64]
        attention_kernel<<<dim3(BB * NHH, SB / 128), 384>>>(pqkv, pattno);
        // y = LN(y + attno @ Wout^T + b)   (fused)
        gemm64_ln<<<BSR / 64, 256>>>(
            pattno, attn_out_w + l * DD * DD, attn_out_b + l * DD, py,
            ln1_g + l * DD, ln1_b + l * DD);
        // ff1 = relu(y @ W1^T + b1)  [4608,2048]
        gemm64<1><<<dim3(FFD / 64, BSR / 64), 256>>>(
            py, lin1_w + l * FFD * DD, lin1_b + l * FFD, pff, FFD);
        // ff2 = ff1 @ W2^T + b2  [4608,64], split-K over K=2048
        init_bias64<<<(BSR * DD + 255) / 256, 256>>>(pres, lin2_b + l * DD, BSR * DD);
        gemm_kernel<<<dim3(1, BSR / 64, 8), 256>>>(
            pff, lin2_w + l * DD * FFD, lin2_b + l * DD, pres,
            BSR, DD, FFD, 0);
        // y = LN(y + ff2)
        add_ln_kernel<<<BSR / 8, 256>>>(py, pres, ln2_g + l * DD, ln2_b + l * DD);
    }

    // scores = y @ last_w^T + last_b  [4608,441]
    gemm64<0><<<dim3((KK2 + 63) / 64, BSR / 64), 256>>>(py, last_w, last_b, pff, KK2);
    softmax_t_kernel<<<BSR, 128>>>(pff, kern);
    apply_kernel<<<(BB * CC * HH * WWD + 255) / 256, 256>>>(x, kern, out);
}

// round 8
// speedup vs baseline: 1.4863x; 1.1696x over previous
#include <cuda_runtime.h>

// ---------------- problem constants ----------------
#define SB    2304          // S = H*W
#define BSR   4608          // B*S
#define DD    64
#define NHH   8
#define HDD   8
#define FFD   2048
#define NLAYER 8
#define KS    21
#define KK2   441
#define HH    48
#define WWD   48
#define CC    3
#define BB    2
#define EPSV  1e-5f

typedef unsigned long long u64;

// ---------------- scratch ----------------
__device__ float g_y[BSR * DD];
__device__ float g_qkv[BSR * 3 * DD];
__device__ float g_attno[BSR * DD];
__device__ float g_res[BSR * DD];
__device__ float g_ff[BSR * FFD];

// ---------------- packed f32x2 helpers ----------------
__device__ __forceinline__ u64 fma2(u64 a, u64 b, u64 c) {
    u64 d;
    asm("fma.rn.f32x2 %0, %1, %2, %3;" : "=l"(d) : "l"(a), "l"(b), "l"(c));
    return d;
}
__device__ __forceinline__ u64 mul2(u64 a, u64 b) {
    u64 d;
    asm("mul.rn.f32x2 %0, %1, %2;" : "=l"(d) : "l"(a), "l"(b));
    return d;
}
__device__ __forceinline__ u64 pack2(float lo, float hi) {
    u64 d;
    asm("mov.b64 %0, {%1, %2};" : "=l"(d) : "r"(__float_as_uint(lo)), "r"(__float_as_uint(hi)));
    return d;
}
__device__ __forceinline__ void unpack2(u64 v, float& lo, float& hi) {
    unsigned a, b;
    asm("mov.b64 {%0, %1}, %2;" : "=r"(a), "=r"(b) : "l"(v));
    lo = __uint_as_float(a); hi = __uint_as_float(b);
}
__device__ __forceinline__ float ex2f(float x) {
    float r;
    asm("ex2.approx.f32 %0, %1;" : "=f"(r) : "f"(x));
    return r;
}

// ---------------- conv 3x3 + BN + ReLU -> [B,S,D] ----------------
__global__ __launch_bounds__(256) void conv_bn_relu(
    const float* __restrict__ x, const float* __restrict__ w,
    const float* __restrict__ cb, const float* __restrict__ gma,
    const float* __restrict__ bta, const float* __restrict__ mean,
    const float* __restrict__ var, float* __restrict__ y)
{
    int idx = blockIdx.x * 256 + threadIdx.x;
    if (idx >= BSR * DD) return;
    int d = idx & 63;
    int s = (idx >> 6) % SB;
    int b = idx / (SB * DD);
    int hh = s / WWD, ww = s % WWD;
    float sum = cb[d];
    #pragma unroll
    for (int ci = 0; ci < 3; ci++) {
        #pragma unroll
        for (int kh = 0; kh < 3; kh++) {
            int ih = hh + kh - 1;
            if ((unsigned)ih >= HH) continue;
            #pragma unroll
            for (int kw = 0; kw < 3; kw++) {
                int iw = ww + kw - 1;
                if ((unsigned)iw >= WWD) continue;
                sum += x[((b * CC + ci) * HH + ih) * WWD + iw] *
                       w[((d * CC + ci) * 3 + kh) * 3 + kw];
            }
        }
    }
    sum = (sum - mean[d]) * rsqrtf(var[d] + EPSV) * gma[d] + bta[d];
    y[idx] = fmaxf(sum, 0.0f);
}

// ---------------- gemm64: C[M,N] = A[M,64] @ W[N,64]^T + bias (FFMA2) ----------
// 64x64 tile, 256 threads, 4x4 per-thread (row-paired f32x2 accumulators).
template<int RELU>
__global__ __launch_bounds__(256) void gemm64(
    const float* __restrict__ A, const float* __restrict__ W,
    const float* __restrict__ bias, float* __restrict__ C, int N)
{
    __shared__ __align__(16) float As[64][68];
    __shared__ __align__(16) float Ws[64][68];
    int tid = threadIdx.x;
    int rowBase = blockIdx.y * 64;
    int nBase = blockIdx.x * 64;

    int r = tid >> 2, qd = tid & 3;
    {
        const float* ap = A + (rowBase + r) * 64 + qd * 4;
        #pragma unroll
        for (int j = 0; j < 4; j++) {
            float4 v = *(const float4*)(ap + j * 16);
            int k = qd * 4 + j * 16;
            As[k][r] = v.x; As[k + 1][r] = v.y; As[k + 2][r] = v.z; As[k + 3][r] = v.w;
        }
        int n = nBase + r;
        if (n < N) {
            const float* wp = W + n * 64 + qd * 4;
            #pragma unroll
            for (int j = 0; j < 4; j++) {
                float4 v = *(const float4*)(wp + j * 16);
                int k = qd * 4 + j * 16;
                Ws[k][r] = v.x; Ws[k + 1][r] = v.y; Ws[k + 2][r] = v.z; Ws[k + 3][r] = v.w;
            }
        } else {
            #pragma unroll
            for (int j = 0; j < 4; j++) {
                int k = qd * 4 + j * 16;
                Ws[k][r] = 0.f; Ws[k + 1][r] = 0.f; Ws[k + 2][r] = 0.f; Ws[k + 3][r] = 0.f;
            }
        }
    }
    __syncthreads();

    int tx = tid & 15, ty = tid >> 4;
    u64 acc[2][4] = {};
    #pragma unroll
    for (int k = 0; k < 64; k++) {
        double2 a2 = *(const double2*)&As[k][ty * 4];
        u64 a01 = __double_as_longlong(a2.x);
        u64 a23 = __double_as_longlong(a2.y);
        float4 b4 = *(const float4*)&Ws[k][tx * 4];
        u64 b0 = pack2(b4.x, b4.x);
        u64 b1 = pack2(b4.y, b4.y);
        u64 b2 = pack2(b4.z, b4.z);
        u64 b3 = pack2(b4.w, b4.w);
        acc[0][0] = fma2(a01, b0, acc[0][0]);
        acc[0][1] = fma2(a01, b1, acc[0][1]);
        acc[0][2] = fma2(a01, b2, acc[0][2]);
        acc[0][3] = fma2(a01, b3, acc[0][3]);
        acc[1][0] = fma2(a23, b0, acc[1][0]);
        acc[1][1] = fma2(a23, b1, acc[1][1]);
        acc[1][2] = fma2(a23, b2, acc[1][2]);
        acc[1][3] = fma2(a23, b3, acc[1][3]);
    }

    float rv[4][4];
    #pragma unroll
    for (int v = 0; v < 4; v++) {
        unpack2(acc[0][v], rv[0][v], rv[1][v]);
        unpack2(acc[1][v], rv[2][v], rv[3][v]);
    }
    #pragma unroll
    for (int u = 0; u < 4; u++) {
        int row = rowBase + ty * 4 + u;
        #pragma unroll
        for (int v = 0; v < 4; v++) {
            int n = nBase + tx * 4 + v;
            if (n < N) {
                float val = rv[u][v] + bias[n];
                if (RELU) val = fmaxf(val, 0.0f);
                C[row * N + n] = val;
            }
        }
    }
}

// ---------------- gemm64_ln: Y = LN(Y + A @ W^T + bias), N=64, fused ----------
__global__ __launch_bounds__(256) void gemm64_ln(
    const float* __restrict__ A, const float* __restrict__ W,
    const float* __restrict__ bias, float* __restrict__ Y,
    const float* __restrict__ gam, const float* __restrict__ bet)
{
    __shared__ __align__(16) float As[64][68];
    __shared__ __align__(16) float Ws[64][68];
    int tid = threadIdx.x;
    int rowBase = blockIdx.x * 64;

    int r = tid >> 2, qd = tid & 3;
    {
        const float* ap = A + (rowBase + r) * 64 + qd * 4;
        const float* wp = W + r * 64 + qd * 4;
        #pragma unroll
        for (int j = 0; j < 4; j++) {
            float4 va = *(const float4*)(ap + j * 16);
            float4 vw = *(const float4*)(wp + j * 16);
            int k = qd * 4 + j * 16;
            As[k][r] = va.x; As[k + 1][r] = va.y; As[k + 2][r] = va.z; As[k + 3][r] = va.w;
            Ws[k][r] = vw.x; Ws[k + 1][r] = vw.y; Ws[k + 2][r] = vw.z; Ws[k + 3][r] = vw.w;
        }
    }
    __syncthreads();

    int tx = tid & 15, ty = tid >> 4;
    u64 acc[2][4] = {};
    #pragma unroll
    for (int k = 0; k < 64; k++) {
        double2 a2 = *(const double2*)&As[k][ty * 4];
        u64 a01 = __double_as_longlong(a2.x);
        u64 a23 = __double_as_longlong(a2.y);
        float4 b4 = *(const float4*)&Ws[k][tx * 4];
        u64 b0 = pack2(b4.x, b4.x);
        u64 b1 = pack2(b4.y, b4.y);
        u64 b2 = pack2(b4.z, b4.z);
        u64 b3 = pack2(b4.w, b4.w);
        acc[0][0] = fma2(a01, b0, acc[0][0]);
        acc[0][1] = fma2(a01, b1, acc[0][1]);
        acc[0][2] = fma2(a01, b2, acc[0][2]);
        acc[0][3] = fma2(a01, b3, acc[0][3]);
        acc[1][0] = fma2(a23, b0, acc[1][0]);
        acc[1][1] = fma2(a23, b1, acc[1][1]);
        acc[1][2] = fma2(a23, b2, acc[1][2]);
        acc[1][3] = fma2(a23, b3, acc[1][3]);
    }
    float rv[4][4];
    #pragma unroll
    for (int v = 0; v < 4; v++) {
        unpack2(acc[0][v], rv[0][v], rv[1][v]);
        unpack2(acc[1][v], rv[2][v], rv[3][v]);
    }
    __syncthreads();   // done reading Ws; reuse as Z

    #pragma unroll
    for (int u = 0; u < 4; u++) {
        int row = ty * 4 + u;
        float4 yv = *(const float4*)&Y[(rowBase + row) * 64 + tx * 4];
        Ws[row][tx * 4 + 0] = rv[u][0] + bias[tx * 4 + 0] + yv.x;
        Ws[row][tx * 4 + 1] = rv[u][1] + bias[tx * 4 + 1] + yv.y;
        Ws[row][tx * 4 + 2] = rv[u][2] + bias[tx * 4 + 2] + yv.z;
        Ws[row][tx * 4 + 3] = rv[u][3] + bias[tx * 4 + 3] + yv.w;
    }
    __syncthreads();

    int wid = tid >> 5, lane = tid & 31;
    #pragma unroll 1
    for (int i = 0; i < 8; i++) {
        int row = wid * 8 + i;
        float z0 = Ws[row][lane];
        float z1 = Ws[row][lane + 32];
        float s = z0 + z1;
        float ss = z0 * z0 + z1 * z1;
        #pragma unroll
        for (int off = 16; off; off >>= 1) {
            s  += __shfl_xor_sync(0xFFFFFFFFu, s, off);
            ss += __shfl_xor_sync(0xFFFFFFFFu, ss, off);
        }
        float mean = s * (1.0f / 64.0f);
        float var = ss * (1.0f / 64.0f) - mean * mean;
        float inv = rsqrtf(var + EPSV);
        Y[(rowBase + row) * 64 + lane]      = (z0 - mean) * inv * gam[lane]      + bet[lane];
        Y[(rowBase + row) * 64 + 32 + lane] = (z1 - mean) * inv * gam[32 + lane] + bet[32 + lane];
    }
}

// ---------------- lin2 split-K GEMM: C[4608,64] += ff @ W2^T (FFMA2) ----------
__global__ __launch_bounds__(256) void gemm_sk(
    const float* __restrict__ A, const float* __restrict__ W,
    float* __restrict__ C, int K)
{
    __shared__ __align__(16) float As[64][68];
    __shared__ __align__(16) float Ws[64][68];
    int tid = threadIdx.x;
    int rowBase = blockIdx.y * 64;
    int kChunk = K / gridDim.z;
    int kStart = blockIdx.z * kChunk;
    int r = tid >> 2, qd = tid & 3;
    int tx = tid & 15, ty = tid >> 4;

    u64 acc[2][4] = {};
    for (int k0 = kStart; k0 < kStart + kChunk; k0 += 64) {
        __syncthreads();
        const float* ap = A + (rowBase + r) * K + k0 + qd * 4;
        const float* wp = W + r * K + k0 + qd * 4;
        #pragma unroll
        for (int j = 0; j < 4; j++) {
            float4 va = *(const float4*)(ap + j * 16);
            float4 vw = *(const float4*)(wp + j * 16);
            int k = qd * 4 + j * 16;
            As[k][r] = va.x; As[k + 1][r] = va.y; As[k + 2][r] = va.z; As[k + 3][r] = va.w;
            Ws[k][r] = vw.x; Ws[k + 1][r] = vw.y; Ws[k + 2][r] = vw.z; Ws[k + 3][r] = vw.w;
        }
        __syncthreads();
        #pragma unroll
        for (int k = 0; k < 64; k++) {
            double2 a2 = *(const double2*)&As[k][ty * 4];
            u64 a01 = __double_as_longlong(a2.x);
            u64 a23 = __double_as_longlong(a2.y);
            float4 b4 = *(const float4*)&Ws[k][tx * 4];
            u64 b0 = pack2(b4.x, b4.x);
            u64 b1 = pack2(b4.y, b4.y);
            u64 b2 = pack2(b4.z, b4.z);
            u64 b3 = pack2(b4.w, b4.w);
            acc[0][0] = fma2(a01, b0, acc[0][0]);
            acc[0][1] = fma2(a01, b1, acc[0][1]);
            acc[0][2] = fma2(a01, b2, acc[0][2]);
            acc[0][3] = fma2(a01, b3, acc[0][3]);
            acc[1][0] = fma2(a23, b0, acc[1][0]);
            acc[1][1] = fma2(a23, b1, acc[1][1]);
            acc[1][2] = fma2(a23, b2, acc[1][2]);
            acc[1][3] = fma2(a23, b3, acc[1][3]);
        }
    }

    float rv[4][4];
    #pragma unroll
    for (int v = 0; v < 4; v++) {
        unpack2(acc[0][v], rv[0][v], rv[1][v]);
        unpack2(acc[1][v], rv[2][v], rv[3][v]);
    }
    #pragma unroll
    for (int u = 0; u < 4; u++) {
        int row = rowBase + ty * 4 + u;
        #pragma unroll
        for (int v = 0; v < 4; v++)
            atomicAdd(&C[row * 64 + tx * 4 + v], rv[u][v]);
    }
}

__global__ __launch_bounds__(256) void init_bias64(float* __restrict__ C,
                                                   const float* __restrict__ bias, int total)
{
    int i = blockIdx.x * 256 + threadIdx.x;
    if (i < total) C[i] = bias[i & 63];
}

// ---------------- attention: unshifted softmax (small scores), FFMA2 + MUFU ---
// grid (B*NH, S/128), block 384. Group g (128 threads) handles 6 of 18 key tiles.
__global__ __launch_bounds__(384) void attention_kernel(
    const float* __restrict__ qkv, float* __restrict__ o)
{
    __shared__ __align__(16) float Kt[3][128][8];
    __shared__ __align__(16) float Vt[3][128][8];
    __shared__ float Ss[2][128];
    __shared__ float Accs[2][128][8];

    int tid = threadIdx.x;
    int g = tid >> 7;          // 0..2
    int t = tid & 127;
    int bh = blockIdx.x;
    int b = bh >> 3, h = bh & 7;
    int qbase = blockIdx.y * 128;
    int srow = b * SB + qbase + t;

    // q pre-scaled by 1/sqrt(hd) * log2(e) -> scores in log2 domain
    const float QS = 0.35355339059327373f * 1.4426950408889634f;
    const float* qp = qkv + srow * 192 + h * 8;
    float4 qa = *(const float4*)qp;
    float4 qb = *(const float4*)(qp + 4);
    u64 q01 = pack2(qa.x * QS, qa.y * QS);
    u64 q23 = pack2(qa.z * QS, qa.w * QS);
    u64 q45 = pack2(qb.x * QS, qb.y * QS);
    u64 q67 = pack2(qb.z * QS, qb.w * QS);

    float sum = 0.0f;
    u64 a01 = 0, a23 = 0, a45 = 0, a67 = 0;

    for (int tile = g; tile < 18; tile += 3) {
        int krow = b * SB + tile * 128 + t;
        const float* kp = qkv + krow * 192 + 64 + h * 8;
        float4 k0 = *(const float4*)kp;
        float4 k1 = *(const float4*)(kp + 4);
        float4 v0 = *(const float4*)(kp + 64);
        float4 v1 = *(const float4*)(kp + 68);
        *(float4*)&Kt[g][t][0] = k0; *(float4*)&Kt[g][t][4] = k1;
        *(float4*)&Vt[g][t][0] = v0; *(float4*)&Vt[g][t][4] = v1;
        asm volatile("bar.sync %0, 128;" :: "r"(g + 1) : "memory");

        #pragma unroll 4
        for (int kk = 0; kk < 128; kk++) {
            double2 ka = *(const double2*)&Kt[g][kk][0];
            double2 kb2 = *(const double2*)&Kt[g][kk][4];
            u64 d = mul2(q01, __double_as_longlong(ka.x));
            d = fma2(q23, __double_as_longlong(ka.y), d);
            d = fma2(q45, __double_as_longlong(kb2.x), d);
            d = fma2(q67, __double_as_longlong(kb2.y), d);
            float lo, hi;
            unpack2(d, lo, hi);
            float s = fminf(lo + hi, 80.0f);
            float e = ex2f(s);
            sum += e;
            u64 pe = pack2(e, e);
            double2 va = *(const double2*)&Vt[g][kk][0];
            double2 vb2 = *(const double2*)&Vt[g][kk][4];
            a01 = fma2(pe, __double_as_longlong(va.x), a01);
            a23 = fma2(pe, __double_as_longlong(va.y), a23);
            a45 = fma2(pe, __double_as_longlong(vb2.x), a45);
            a67 = fma2(pe, __double_as_longlong(vb2.y), a67);
        }
        asm volatile("bar.sync %0, 128;" :: "r"(g + 1) : "memory");
    }

    float av[8];
    unpack2(a01, av[0], av[1]);
    unpack2(a23, av[2], av[3]);
    unpack2(a45, av[4], av[5]);
    unpack2(a67, av[6], av[7]);

    if (g > 0) {
        Ss[g - 1][t] = sum;
        #pragma unroll
        for (int j = 0; j < 8; j++) Accs[g - 1][t][j] = av[j];
    }
    __syncthreads();
    if (g == 0) {
        sum += Ss[0][t] + Ss[1][t];
        #pragma unroll
        for (int j = 0; j < 8; j++)
            av[j] += Accs[0][t][j] + Accs[1][t][j];
        float inv = 1.0f / sum;
        float* op = o + srow * 64 + h * 8;
        float4 o0 = make_float4(av[0]*inv, av[1]*inv, av[2]*inv, av[3]*inv);
        float4 o1 = make_float4(av[4]*inv, av[5]*inv, av[6]*inv, av[7]*inv);
        *(float4*)op = o0;
        *(float4*)(op + 4) = o1;
    }
}

// ---------------- residual add + LayerNorm, warp per row ----------------
__global__ __launch_bounds__(256) void add_ln_kernel(
    float* __restrict__ y, const float* __restrict__ r,
    const float* __restrict__ g, const float* __restrict__ b)
{
    int row = blockIdx.x * 8 + (threadIdx.x >> 5);
    int lane = threadIdx.x & 31;
    float z0 = y[row * 64 + lane] + r[row * 64 + lane];
    float z1 = y[row * 64 + 32 + lane] + r[row * 64 + 32 + lane];
    float s = z0 + z1;
    float ss = z0 * z0 + z1 * z1;
    #pragma unroll
    for (int off = 16; off; off >>= 1) {
        s  += __shfl_xor_sync(0xFFFFFFFFu, s, off);
        ss += __shfl_xor_sync(0xFFFFFFFFu, ss, off);
    }
    float mean = s * (1.0f / 64.0f);
    float var = ss * (1.0f / 64.0f) - mean * mean;
    float inv = rsqrtf(var + EPSV);
    y[row * 64 + lane]      = (z0 - mean) * inv * g[lane]      + b[lane];
    y[row * 64 + 32 + lane] = (z1 - mean) * inv * g[32 + lane] + b[32 + lane];
}

// ---------------- final softmax over 441 + transpose to [B,441,S] ----------
__global__ __launch_bounds__(128) void softmax_t_kernel(
    const float* __restrict__ sc, float* __restrict__ outK)
{
    __shared__ float red[128];
    int row = blockIdx.x;
    int b = row / SB, s = row % SB;
    int tid = threadIdx.x;
    float v[4];
    float mx = -1e30f;
    #pragma unroll
    for (int i = 0; i < 4; i++) {
        int p = tid + i * 128;
        v[i] = (p < KK2) ? sc[row * KK2 + p] : -1e30f;
        mx = fmaxf(mx, v[i]);
    }
    red[tid] = mx; __syncthreads();
    for (int o = 64; o; o >>= 1) { if (tid < o) red[tid] = fmaxf(red[tid], red[tid + o]); __syncthreads(); }
    float m = red[0]; __syncthreads();
    float sum = 0.0f;
    #pragma unroll
    for (int i = 0; i < 4; i++) {
        int p = tid + i * 128;
        v[i] = (p < KK2) ? __expf(v[i] - m) : 0.0f;
        sum += v[i];
    }
    red[tid] = sum; __syncthreads();
    for (int o = 64; o; o >>= 1) { if (tid < o) red[tid] += red[tid + o]; __syncthreads(); }
    float inv = 1.0f / red[0];
    #pragma unroll
    for (int i = 0; i < 4; i++) {
        int p = tid + i * 128;
        if (p < KK2) outK[(b * KK2 + p) * SB + s] = v[i] * inv;
    }
}

// ---------------- apply predicted kernel (reflect pad) ----------------
__global__ __launch_bounds__(256) void apply_kernel(
    const float* __restrict__ x, const float* __restrict__ kern, float* __restrict__ out)
{
    int idx = blockIdx.x * 256 + threadIdx.x;
    if (idx >= BB * CC * HH * WWD) return;
    int ww = idx % WWD;
    int hh = (idx / WWD) % HH;
    int c = (idx / (HH * WWD)) % CC;
    int b = idx / (CC * HH * WWD);
    const float* kb = kern + b * KK2 * SB + hh * WWD + ww;
    const float* xb = x + (b * CC + c) * HH * WWD;
    float acc = 0.0f;
    #pragma unroll 1
    for (int kh = 0; kh < KS; kh++) {
        int ih = hh + kh - 10;
        if (ih < 0) ih = -ih;
        else if (ih >= HH) ih = 2 * HH - 2 - ih;
        const float* xr = xb + ih * WWD;
        #pragma unroll
        for (int kw = 0; kw < KS; kw++) {
            int iw = ww + kw - 10;
            if (iw < 0) iw = -iw;
            else if (iw >= WWD) iw = 2 * WWD - 2 - iw;
            acc = fmaf(xr[iw], kb[(kh * KS + kw) * SB], acc);
        }
    }
    out[idx] = acc;
}

// ---------------- host launcher ----------------
extern "C" void kernel_launch(void* const* d_in, const int* in_sizes, int n_in,
                              void* d_out, int out_size)
{
    const float* x        = (const float*)d_in[0];
    const float* conv1_w  = (const float*)d_in[1];
    const float* conv1_b  = (const float*)d_in[2];
    const float* bn_gamma = (const float*)d_in[3];
    const float* bn_beta  = (const float*)d_in[4];
    const float* bn_mean  = (const float*)d_in[5];
    const float* bn_var   = (const float*)d_in[6];
    const float* attn_in_w  = (const float*)d_in[7];
    const float* attn_in_b  = (const float*)d_in[8];
    const float* attn_out_w = (const float*)d_in[9];
    const float* attn_out_b = (const float*)d_in[10];
    const float* lin1_w   = (const float*)d_in[11];
    const float* lin1_b   = (const float*)d_in[12];
    const float* lin2_w   = (const float*)d_in[13];
    const float* lin2_b   = (const float*)d_in[14];
    const float* ln1_g    = (const float*)d_in[15];
    const float* ln1_b    = (const float*)d_in[16];
    const float* ln2_g    = (const float*)d_in[17];
    const float* ln2_b    = (const float*)d_in[18];
    const float* last_w   = (const float*)d_in[19];
    const float* last_b   = (const float*)d_in[20];

    float* out = (float*)d_out;
    float* kern = out + BB * CC * HH * WWD;

    float *py, *pqkv, *pattno, *pres, *pff;
    cudaGetSymbolAddress((void**)&py, g_y);
    cudaGetSymbolAddress((void**)&pqkv, g_qkv);
    cudaGetSymbolAddress((void**)&pattno, g_attno);
    cudaGetSymbolAddress((void**)&pres, g_res);
    cudaGetSymbolAddress((void**)&pff, g_ff);

    conv_bn_relu<<<(BSR * DD + 255) / 256, 256>>>(x, conv1_w, conv1_b, bn_gamma,
                                                  bn_beta, bn_mean, bn_var, py);

    for (int l = 0; l < NLAYER; l++) {
        // qkv = y @ Win^T + b   [4608,192]
        gemm64<0><<<dim3(3, BSR / 64), 256>>>(
            py, attn_in_w + l * 192 * DD, attn_in_b + l * 192, pqkv, 192);
        // attention -> attno [4608,64]
        attention_kernel<<<dim3(BB * NHH, SB / 128), 384>>>(pqkv, pattno);
        // y = LN(y + attno @ Wout^T + b)   (fused)
        gemm64_ln<<<BSR / 64, 256>>>(
            pattno, attn_out_w + l * DD * DD, attn_out_b + l * DD, py,
            ln1_g + l * DD, ln1_b + l * DD);
        // ff1 = relu(y @ W1^T + b1)  [4608,2048]
        gemm64<1><<<dim3(FFD / 64, BSR / 64), 256>>>(
            py, lin1_w + l * FFD * DD, lin1_b + l * FFD, pff, FFD);
        // ff2 = ff1 @ W2^T + b2  [4608,64], split-K over K=2048
        init_bias64<<<(BSR * DD + 255) / 256, 256>>>(pres, lin2_b + l * DD, BSR * DD);
        gemm_sk<<<dim3(1, BSR / 64, 8), 256>>>(pff, lin2_w + l * DD * FFD, pres, FFD);
        // y = LN(y + ff2)
        add_ln_kernel<<<BSR / 8, 256>>>(py, pres, ln2_g + l * DD, ln2_b + l * DD);
    }

    // scores = y @ last_w^T + last_b  [4608,441]
    gemm64<0><<<dim3((KK2 + 63) / 64, BSR / 64), 256>>>(py, last_w, last_b, pff, KK2);
    softmax_t_kernel<<<BSR, 128>>>(pff, kern);
    apply_kernel<<<(BB * CC * HH * WWD + 255) / 256, 256>>>(x, kern, out);
}